// round 1
// baseline (speedup 1.0000x reference)
#include <cuda_runtime.h>
#include <math.h>
#include <float.h>

#define NPART 62
#define MM    512
#define DD    256
#define TM    64
#define TN    64
#define TD    32
#define MARGIN 0.2f

// scratch (device globals — no allocation allowed)
__device__ float g_sq[NPART * MM];
__device__ float g_loss[NPART * 8];
__device__ float g_dist[NPART * 8];

// ---------------------------------------------------------------------------
// Kernel 1: squared norms per row. One warp per row (256 floats = 64 float4).
// ---------------------------------------------------------------------------
__global__ void sq_kernel(const float* __restrict__ f) {
    int row = blockIdx.x * blockDim.y + threadIdx.y;
    if (row >= NPART * MM) return;
    const float4* p = (const float4*)(f + (size_t)row * DD);
    int lane = threadIdx.x;
    float s = 0.f;
#pragma unroll
    for (int q = 0; q < 2; q++) {
        float4 v = p[lane + q * 32];
        s += v.x * v.x + v.y * v.y + v.z * v.z + v.w * v.w;
    }
#pragma unroll
    for (int o = 16; o; o >>= 1) s += __shfl_xor_sync(0xFFFFFFFFu, s, o);
    if (lane == 0) g_sq[row] = s;
}

// ---------------------------------------------------------------------------
// Kernel 2: per (part n, m-tile) block computes the 64x512 strip of the
// distance matrix via tiled fp32 GEMM, with fused hard-pos/hard-neg/sum
// epilogue. Labels are m//8 and tiles are 64-aligned, so positives only
// occur when the j-tile equals the m-tile.
// ---------------------------------------------------------------------------
__global__ __launch_bounds__(256, 2) void tile_kernel(const float* __restrict__ f) {
    __shared__ float As[TD][TM + 4];   // d-major, padded for LDS.128 alignment
    __shared__ float Bs[TD][TN + 4];
    __shared__ float red_hp[TM][17];
    __shared__ float red_hn[TM][17];
    __shared__ float red_buf[256];
    __shared__ float loss_buf[64];

    const int n  = blockIdx.y;
    const int m0 = blockIdx.x * TM;
    const int tid = threadIdx.x;
    const int ti = tid & 15;           // 16 row-thread positions
    const int tj = tid >> 4;           // 16 col-thread positions

    const float* fn = f + (size_t)n * MM * DD;
    const float* sqn = g_sq + n * MM;

    float sq_row[4];
#pragma unroll
    for (int r = 0; r < 4; r++) sq_row[r] = sqn[m0 + ti * 4 + r];

    float hp[4], hn[4];
#pragma unroll
    for (int r = 0; r < 4; r++) { hp[r] = -FLT_MAX; hn[r] = FLT_MAX; }
    float dsum = 0.f;

    for (int jt = 0; jt < MM / TN; jt++) {
        const int j0 = jt * TN;
        float acc[4][4];
#pragma unroll
        for (int r = 0; r < 4; r++)
#pragma unroll
            for (int c = 0; c < 4; c++) acc[r][c] = 0.f;

        for (int dc = 0; dc < DD / TD; dc++) {
            const int d0 = dc * TD;
            __syncthreads();  // protect smem from previous iteration's readers
            // load 32x64 A and B chunks, transposed to d-major. 512 float4
            // each over 256 threads -> 2 per thread, fully coalesced.
#pragma unroll
            for (int l = 0; l < 2; l++) {
                int idx = tid + l * 256;
                int i = idx >> 3;      // 0..63 row within tile
                int q = idx & 7;       // float4 index within 32 d's
                float4 v = *(const float4*)(fn + (size_t)(m0 + i) * DD + d0 + q * 4);
                As[q * 4 + 0][i] = v.x; As[q * 4 + 1][i] = v.y;
                As[q * 4 + 2][i] = v.z; As[q * 4 + 3][i] = v.w;
                float4 w = *(const float4*)(fn + (size_t)(j0 + i) * DD + d0 + q * 4);
                Bs[q * 4 + 0][i] = w.x; Bs[q * 4 + 1][i] = w.y;
                Bs[q * 4 + 2][i] = w.z; Bs[q * 4 + 3][i] = w.w;
            }
            __syncthreads();
#pragma unroll
            for (int dd = 0; dd < TD; dd++) {
                float4 a = *(const float4*)&As[dd][ti * 4];
                float4 b = *(const float4*)&Bs[dd][tj * 4];
                float av[4] = {a.x, a.y, a.z, a.w};
                float bv[4] = {b.x, b.y, b.z, b.w};
#pragma unroll
                for (int r = 0; r < 4; r++)
#pragma unroll
                    for (int c = 0; c < 4; c++)
                        acc[r][c] = fmaf(av[r], bv[c], acc[r][c]);
            }
        }

        // epilogue for this 64x64 gram tile
        float sq_col[4];
#pragma unroll
        for (int c = 0; c < 4; c++) sq_col[c] = sqn[j0 + tj * 4 + c];
#pragma unroll
        for (int r = 0; r < 4; r++) {
            const int gi = m0 + ti * 4 + r;
#pragma unroll
            for (int c = 0; c < 4; c++) {
                const int gj = j0 + tj * 4 + c;
                float d2 = sq_row[r] + sq_col[c] - 2.f * acc[r][c];
                float dist = sqrtf(fmaxf(d2, 0.f));
                dsum += dist;
                if ((gi >> 3) == (gj >> 3)) hp[r] = fmaxf(hp[r], dist);
                else                        hn[r] = fminf(hn[r], dist);
            }
        }
    }

    // cross-thread reduction: rows are split across the 16 tj positions
#pragma unroll
    for (int r = 0; r < 4; r++) {
        red_hp[ti * 4 + r][tj] = hp[r];
        red_hn[ti * 4 + r][tj] = hn[r];
    }
    red_buf[tid] = dsum;
    __syncthreads();

    for (int s = 128; s > 0; s >>= 1) {
        if (tid < s) red_buf[tid] += red_buf[tid + s];
        __syncthreads();
    }

    if (tid < 64) {
        float h = -FLT_MAX, l = FLT_MAX;
#pragma unroll
        for (int t = 0; t < 16; t++) {
            h = fmaxf(h, red_hp[tid][t]);
            l = fminf(l, red_hn[tid][t]);
        }
        loss_buf[tid] = fmaxf(MARGIN + h - l, 0.f);
    }
    __syncthreads();
    if (tid < 32) {
        float v = loss_buf[tid] + loss_buf[tid + 32];
#pragma unroll
        for (int o = 16; o; o >>= 1) v += __shfl_xor_sync(0xFFFFFFFFu, v, o);
        if (tid == 0) {
            g_loss[n * 8 + blockIdx.x] = v;
            g_dist[n * 8 + blockIdx.x] = red_buf[0];
        }
    }
}

// ---------------------------------------------------------------------------
// Kernel 3: combine the 8 m-tile partials per part into the final outputs.
// out[0:62] = hard_loss_mean, out[62:124] = dist_mean.
// ---------------------------------------------------------------------------
__global__ void finish_kernel(float* __restrict__ out) {
    int n = threadIdx.x;
    if (n < NPART) {
        float ls = 0.f, ds = 0.f;
#pragma unroll
        for (int t = 0; t < 8; t++) { ls += g_loss[n * 8 + t]; ds += g_dist[n * 8 + t]; }
        out[n]         = ls / (float)MM;
        out[NPART + n] = ds / ((float)MM * (float)MM);
    }
}

extern "C" void kernel_launch(void* const* d_in, const int* in_sizes, int n_in,
                              void* d_out, int out_size) {
    const float* feature = (const float*)d_in[0];
    float* out = (float*)d_out;

    // squared norms: warp per row, 8 rows per block
    dim3 b1(32, 8);
    int rows = NPART * MM;
    sq_kernel<<<(rows + 7) / 8, b1>>>(feature);

    // main tiled distance + triplet epilogue
    dim3 grid(MM / TM, NPART);
    tile_kernel<<<grid, 256>>>(feature);

    // final reduction
    finish_kernel<<<1, 64>>>(out);
}

// round 3
// speedup vs baseline: 2.8915x; 2.8915x over previous
#include <cuda_runtime.h>
#include <cuda_bf16.h>
#include <math.h>
#include <float.h>
#include <stdint.h>

#define NPART 62
#define MM    512
#define DD    256
#define MT    64           // rows per CTA
#define MARGIN 0.2f

// smem layout (bytes)
#define A_STRIDE 528       // 256 bf16 (512B) + 16B pad  -> conflict-free ldmatrix
#define B_STRIDE 80        // 32 bf16 (64B) + 16B pad
#define SM_A_HI  0
#define SM_A_LO  33792     // 64 * 528
#define SM_B     67584     // + buf*20480 + plane*10240 (2 bufs x 2 planes x 128*80)
#define SM_SQ    108544    // 512 floats
#define SM_TOTAL 110592
#define SM_RED   SM_B      // reduction scratch reuses B area after mainloop

// global scratch (no allocation allowed)
__device__ __align__(16) __nv_bfloat16 g_hi[(size_t)NPART * MM * DD];
__device__ __align__(16) __nv_bfloat16 g_lo[(size_t)NPART * MM * DD];
__device__ __align__(16) float g_sq[NPART * MM];
__device__ float g_loss[NPART * 8];
__device__ float g_dist[NPART * 8];

__device__ __forceinline__ uint32_t smem_u32(const void* p) {
    uint32_t a;
    asm("{ .reg .u64 t; cvta.to.shared.u64 t, %1; cvt.u32.u64 %0, t; }" : "=r"(a) : "l"(p));
    return a;
}
__device__ __forceinline__ void cp16(uint32_t dst, const void* src) {
    asm volatile("cp.async.cg.shared.global [%0], [%1], 16;" :: "r"(dst), "l"(src));
}
#define CP_COMMIT() asm volatile("cp.async.commit_group;" ::: "memory")
#define CP_WAIT(n)  asm volatile("cp.async.wait_group %0;" :: "n"(n) : "memory")

__device__ __forceinline__ void ldm_x4(uint32_t* r, uint32_t addr) {
    asm volatile("ldmatrix.sync.aligned.m8n8.x4.shared.b16 {%0,%1,%2,%3}, [%4];"
                 : "=r"(r[0]), "=r"(r[1]), "=r"(r[2]), "=r"(r[3]) : "r"(addr));
}
__device__ __forceinline__ void mma16816(float* c, const uint32_t* a, const uint32_t* b) {
    asm volatile("mma.sync.aligned.m16n8k16.row.col.f32.bf16.bf16.f32 "
                 "{%0,%1,%2,%3}, {%4,%5,%6,%7}, {%8,%9}, {%0,%1,%2,%3};"
                 : "+f"(c[0]), "+f"(c[1]), "+f"(c[2]), "+f"(c[3])
                 : "r"(a[0]), "r"(a[1]), "r"(a[2]), "r"(a[3]), "r"(b[0]), "r"(b[1]));
}

// ---------------------------------------------------------------------------
// Kernel 1: per row: exact fp32 sq-norm + split-bf16 hi/lo planes.
// ---------------------------------------------------------------------------
__global__ void prep_kernel(const float* __restrict__ f) {
    int row = blockIdx.x * blockDim.y + threadIdx.y;
    if (row >= NPART * MM) return;
    int lane = threadIdx.x;
    const float4* p = (const float4*)(f + (size_t)row * DD);
    float s = 0.f;
#pragma unroll
    for (int q = 0; q < 2; q++) {
        float4 v = p[lane + q * 32];
        int col = (lane + q * 32) * 4;
        __nv_bfloat162 h01 = __floats2bfloat162_rn(v.x, v.y);
        __nv_bfloat162 h23 = __floats2bfloat162_rn(v.z, v.w);
        float2 f01 = __bfloat1622float2(h01);
        float2 f23 = __bfloat1622float2(h23);
        __nv_bfloat162 l01 = __floats2bfloat162_rn(v.x - f01.x, v.y - f01.y);
        __nv_bfloat162 l23 = __floats2bfloat162_rn(v.z - f23.x, v.w - f23.y);
        size_t off = (size_t)row * DD + col;
        *(__nv_bfloat162*)(g_hi + off)     = h01;
        *(__nv_bfloat162*)(g_hi + off + 2) = h23;
        *(__nv_bfloat162*)(g_lo + off)     = l01;
        *(__nv_bfloat162*)(g_lo + off + 2) = l23;
        s += v.x * v.x + v.y * v.y + v.z * v.z + v.w * v.w;
    }
#pragma unroll
    for (int o = 16; o; o >>= 1) s += __shfl_xor_sync(0xFFFFFFFFu, s, o);
    if (lane == 0) g_sq[row] = s;
}

// ---------------------------------------------------------------------------
// Kernel 2: CTA = (part n, 64-row m-tile). Sweeps all 512 cols in 4 j-tiles
// of 128; K=256 resident for A, B double-buffered in 32-k chunks via cp.async.
// Split-bf16 -> 3 MMAs per (frag, k16). Fused dist/hard-pos/neg epilogue.
// ---------------------------------------------------------------------------
__global__ void __launch_bounds__(256, 2) gemm_kernel() {
    extern __shared__ char smem[];
    uint32_t sb = smem_u32(smem);
    const int tid  = threadIdx.x;
    const int wid  = tid >> 5;
    const int lane = tid & 31;
    const int wr = wid >> 2;           // 0..1 : which 32-row group
    const int wc = wid & 3;            // 0..3 : which 32-col group in j-tile
    const int mt = blockIdx.x;
    const int n  = blockIdx.y;
    const int m0 = mt * MT;

    const __nv_bfloat16* hi_n = g_hi + (size_t)n * MM * DD;
    const __nv_bfloat16* lo_n = g_lo + (size_t)n * MM * DD;

    // ---- prologue loads: sq (512 f32), A hi/lo (64x256), B chunk 0 ----
    for (int i = tid; i < 128; i += 256)
        cp16(sb + SM_SQ + i * 16, g_sq + n * MM + i * 4);
#pragma unroll
    for (int c = tid; c < 4096; c += 256) {
        int plane = c >> 11, idx = c & 2047;
        int row = idx >> 5, q = idx & 31;
        const __nv_bfloat16* src = (plane ? lo_n : hi_n) + (size_t)(m0 + row) * DD + q * 8;
        cp16(sb + (plane ? SM_A_LO : SM_A_HI) + row * A_STRIDE + q * 16, src);
    }
    // B chunk for step 0 (jt=0, kc=0) into buffer 0
    {
#pragma unroll
        for (int c = tid; c < 1024; c += 256) {
            int plane = c >> 9, idx = c & 511;
            int row = idx >> 2, q = idx & 3;
            const __nv_bfloat16* src = (plane ? lo_n : hi_n) + (size_t)row * DD + q * 8;
            cp16(sb + SM_B + plane * 10240 + row * B_STRIDE + q * 16, src);
        }
    }
    CP_COMMIT();

    // ldmatrix address precompute
    const uint32_t a_off = (uint32_t)(lane & 15) * A_STRIDE + (uint32_t)(lane >> 4) * 16;
    uint32_t aaddr[2];
#pragma unroll
    for (int f = 0; f < 2; f++)
        aaddr[f] = sb + (uint32_t)(wr * 32 + f * 16) * A_STRIDE + a_off;
    const uint32_t b_off = (uint32_t)((lane & 7) + ((lane >> 4) & 1) * 8) * B_STRIDE
                         + (uint32_t)((lane >> 3) & 1) * 16;
    uint32_t baddr[2];
#pragma unroll
    for (int g = 0; g < 2; g++)
        baddr[g] = (uint32_t)(wc * 32 + g * 16) * B_STRIDE + b_off;

    float hp[4], hn[4];
#pragma unroll
    for (int s = 0; s < 4; s++) { hp[s] = -FLT_MAX; hn[s] = FLT_MAX; }
    float dsum = 0.f;
    float acc[2][4][4];

#pragma unroll 1
    for (int step = 0; step < 32; step++) {
        const int jt = step >> 3, kc = step & 7;
        // prefetch next chunk into alternate buffer
        if (step + 1 < 32) {
            const int jt2 = (step + 1) >> 3, kc2 = (step + 1) & 7;
            const int j0n = jt2 * 128, k0n = kc2 * 32;
            const uint32_t bufn = ((step + 1) & 1) * 20480;
#pragma unroll
            for (int c = tid; c < 1024; c += 256) {
                int plane = c >> 9, idx = c & 511;
                int row = idx >> 2, q = idx & 3;
                const __nv_bfloat16* src =
                    (plane ? lo_n : hi_n) + (size_t)(j0n + row) * DD + k0n + q * 8;
                cp16(sb + SM_B + bufn + plane * 10240 + row * B_STRIDE + q * 16, src);
            }
            CP_COMMIT();
            CP_WAIT(1);
        } else {
            CP_WAIT(0);
        }
        __syncthreads();

        if (kc == 0) {
#pragma unroll
            for (int mi = 0; mi < 2; mi++)
#pragma unroll
                for (int ni = 0; ni < 4; ni++)
#pragma unroll
                    for (int r = 0; r < 4; r++) acc[mi][ni][r] = 0.f;
        }

        const uint32_t bbase = sb + SM_B + (uint32_t)(step & 1) * 20480;
#pragma unroll
        for (int ks = 0; ks < 2; ks++) {
            const uint32_t akb = (uint32_t)(kc * 32 + ks * 16) * 2;
            uint32_t ahi[2][4], alo[2][4];
#pragma unroll
            for (int f = 0; f < 2; f++) {
                ldm_x4(ahi[f], aaddr[f] + akb);
                ldm_x4(alo[f], aaddr[f] + akb + (SM_A_LO - SM_A_HI));
            }
            uint32_t bhi[2][4], blo[2][4];
#pragma unroll
            for (int g = 0; g < 2; g++) {
                ldm_x4(bhi[g], bbase + baddr[g] + ks * 32);
                ldm_x4(blo[g], bbase + baddr[g] + ks * 32 + 10240);
            }
#pragma unroll
            for (int mi = 0; mi < 2; mi++)
#pragma unroll
                for (int ni = 0; ni < 4; ni++) {
                    const int g = ni >> 1, o = (ni & 1) * 2;
                    mma16816(acc[mi][ni], ahi[mi], &bhi[g][o]);
                    mma16816(acc[mi][ni], ahi[mi], &blo[g][o]);
                    mma16816(acc[mi][ni], alo[mi], &bhi[g][o]);
                }
        }

        if (kc == 7) {
            // epilogue for j-tile jt: dist + hard pos/neg + sum
            const float* sq_s = (const float*)(smem + SM_SQ);
            const int j0 = jt * 128;
#pragma unroll
            for (int mi = 0; mi < 2; mi++)
#pragma unroll
                for (int ni = 0; ni < 4; ni++)
#pragma unroll
                    for (int r = 0; r < 4; r++) {
                        const int rowl = wr * 32 + mi * 16 + (r >> 1) * 8 + (lane >> 2);
                        const int col  = j0 + wc * 32 + ni * 8 + (lane & 3) * 2 + (r & 1);
                        const int gi   = m0 + rowl;
                        float d2 = sq_s[gi] + sq_s[col] - 2.f * acc[mi][ni][r];
                        float dist = sqrtf(fmaxf(d2, 0.f));
                        dsum += dist;
                        const int slot = mi * 2 + (r >> 1);
                        if ((gi >> 3) == (col >> 3)) hp[slot] = fmaxf(hp[slot], dist);
                        else                         hn[slot] = fminf(hn[slot], dist);
                    }
        }
        __syncthreads();
    }

    // ---- block reduction (reuse B area) ----
    float* hpr  = (float*)(smem + SM_RED);          // [64][4]
    float* hnr  = hpr + 256;
    float* rsum = hnr + 256;                        // [256]
    float* lb   = rsum + 256;                       // [64]
#pragma unroll
    for (int s = 0; s < 4; s++) {
        float h = hp[s], l = hn[s];
        h = fmaxf(h, __shfl_xor_sync(0xFFFFFFFFu, h, 1));
        h = fmaxf(h, __shfl_xor_sync(0xFFFFFFFFu, h, 2));
        l = fminf(l, __shfl_xor_sync(0xFFFFFFFFu, l, 1));
        l = fminf(l, __shfl_xor_sync(0xFFFFFFFFu, l, 2));
        if ((lane & 3) == 0) {
            const int rowl = wr * 32 + (s >> 1) * 16 + (s & 1) * 8 + (lane >> 2);
            hpr[rowl * 4 + wc] = h;
            hnr[rowl * 4 + wc] = l;
        }
    }
    rsum[tid] = dsum;
    __syncthreads();
    if (tid < 64) {
        float H = -FLT_MAX, L = FLT_MAX;
#pragma unroll
        for (int c = 0; c < 4; c++) {
            H = fmaxf(H, hpr[tid * 4 + c]);
            L = fminf(L, hnr[tid * 4 + c]);
        }
        lb[tid] = fmaxf(MARGIN + H - L, 0.f);
    }
    __syncthreads();
    for (int s = 128; s > 0; s >>= 1) {
        if (tid < s) rsum[tid] += rsum[tid + s];
        __syncthreads();
    }
    for (int s = 32; s > 0; s >>= 1) {
        if (tid < s) lb[tid] += lb[tid + s];
        __syncthreads();
    }
    if (tid == 0) {
        g_loss[n * 8 + mt] = lb[0];
        g_dist[n * 8 + mt] = rsum[0];
    }
}

// ---------------------------------------------------------------------------
// Kernel 3: combine the 8 m-tile partials per part.
// ---------------------------------------------------------------------------
__global__ void finish_kernel(float* __restrict__ out) {
    int n = threadIdx.x;
    if (n < NPART) {
        float ls = 0.f, ds = 0.f;
#pragma unroll
        for (int t = 0; t < 8; t++) { ls += g_loss[n * 8 + t]; ds += g_dist[n * 8 + t]; }
        out[n]         = ls / (float)MM;
        out[NPART + n] = ds / ((float)MM * (float)MM);
    }
}

extern "C" void kernel_launch(void* const* d_in, const int* in_sizes, int n_in,
                              void* d_out, int out_size) {
    const float* feature = (const float*)d_in[0];
    float* out = (float*)d_out;

    cudaFuncSetAttribute(gemm_kernel, cudaFuncAttributeMaxDynamicSharedMemorySize, SM_TOTAL);

    dim3 b1(32, 8);
    prep_kernel<<<(NPART * MM + 7) / 8, b1>>>(feature);

    dim3 grid(MM / MT, NPART);
    gemm_kernel<<<grid, 256, SM_TOTAL>>>();

    finish_kernel<<<1, 64>>>(out);
}

// round 4
// speedup vs baseline: 4.5379x; 1.5694x over previous
#include <cuda_runtime.h>
#include <cuda_bf16.h>
#include <math.h>
#include <float.h>
#include <stdint.h>

#define NPART 62
#define MM    512
#define DD    256
#define MARGIN 0.2f
#define NTILE 36           // pairs (a<=b) of 8 groups of 64

// smem: 2 buffers x 4 planes x (64 rows x 80B) + sq + reduction scratch
#define PLANE   5120       // 64 * 80
#define BUFSZ   20480      // 4 planes
#define SM_SQ   40960      // 128 floats
#define SM_ROWMIN 41472    // 256 f
#define SM_ROWMAX 42496    // 256 f
#define SM_COLMIN 43520    // 128 f
#define SM_RSUM   44032    // 256 f
#define SM_TOTAL  45056

// global scratch (no allocation allowed)
__device__ __align__(16) __nv_bfloat16 g_hi[(size_t)NPART * MM * DD];
__device__ __align__(16) __nv_bfloat16 g_lo[(size_t)NPART * MM * DD];
__device__ __align__(16) float g_sq[NPART * MM];
__device__ unsigned int g_hn[NPART * MM];    // float bits, atomicMin (dist >= 0)
__device__ float g_hp[NPART * MM];           // written only by diagonal CTAs
__device__ float g_dsum[NPART * NTILE];      // per-tile dist sums (fixed order)

__device__ __forceinline__ uint32_t smem_u32(const void* p) {
    uint32_t a;
    asm("{ .reg .u64 t; cvta.to.shared.u64 t, %1; cvt.u32.u64 %0, t; }" : "=r"(a) : "l"(p));
    return a;
}
__device__ __forceinline__ void cp16(uint32_t dst, const void* src) {
    asm volatile("cp.async.cg.shared.global [%0], [%1], 16;" :: "r"(dst), "l"(src));
}
#define CP_COMMIT() asm volatile("cp.async.commit_group;" ::: "memory")
#define CP_WAIT(n)  asm volatile("cp.async.wait_group %0;" :: "n"(n) : "memory")

__device__ __forceinline__ void ldm_x4(uint32_t* r, uint32_t addr) {
    asm volatile("ldmatrix.sync.aligned.m8n8.x4.shared.b16 {%0,%1,%2,%3}, [%4];"
                 : "=r"(r[0]), "=r"(r[1]), "=r"(r[2]), "=r"(r[3]) : "r"(addr));
}
__device__ __forceinline__ void mma16816(float* c, const uint32_t* a, const uint32_t* b) {
    asm volatile("mma.sync.aligned.m16n8k16.row.col.f32.bf16.bf16.f32 "
                 "{%0,%1,%2,%3}, {%4,%5,%6,%7}, {%8,%9}, {%0,%1,%2,%3};"
                 : "+f"(c[0]), "+f"(c[1]), "+f"(c[2]), "+f"(c[3])
                 : "r"(a[0]), "r"(a[1]), "r"(a[2]), "r"(a[3]), "r"(b[0]), "r"(b[1]));
}
__device__ __forceinline__ void tile_pair(int t, int& a, int& b) {
    int aa = 0, tt = t;
    while (tt >= 8 - aa) { tt -= 8 - aa; aa++; }
    a = aa; b = aa + tt;
}

// ---------------------------------------------------------------------------
// Kernel 1: per row: exact fp32 sq-norm + split-bf16 hi/lo planes.
// ---------------------------------------------------------------------------
__global__ void prep_kernel(const float* __restrict__ f) {
    int row = blockIdx.x * blockDim.y + threadIdx.y;
    if (row >= NPART * MM) return;
    int lane = threadIdx.x;
    const float4* p = (const float4*)(f + (size_t)row * DD);
    float s = 0.f;
#pragma unroll
    for (int q = 0; q < 2; q++) {
        float4 v = p[lane + q * 32];
        int col = (lane + q * 32) * 4;
        __nv_bfloat162 h01 = __floats2bfloat162_rn(v.x, v.y);
        __nv_bfloat162 h23 = __floats2bfloat162_rn(v.z, v.w);
        float2 f01 = __bfloat1622float2(h01);
        float2 f23 = __bfloat1622float2(h23);
        __nv_bfloat162 l01 = __floats2bfloat162_rn(v.x - f01.x, v.y - f01.y);
        __nv_bfloat162 l23 = __floats2bfloat162_rn(v.z - f23.x, v.w - f23.y);
        size_t off = (size_t)row * DD + col;
        *(__nv_bfloat162*)(g_hi + off)     = h01;
        *(__nv_bfloat162*)(g_hi + off + 2) = h23;
        *(__nv_bfloat162*)(g_lo + off)     = l01;
        *(__nv_bfloat162*)(g_lo + off + 2) = l23;
        s += v.x * v.x + v.y * v.y + v.z * v.z + v.w * v.w;
    }
#pragma unroll
    for (int o = 16; o; o >>= 1) s += __shfl_xor_sync(0xFFFFFFFFu, s, o);
    if (lane == 0) g_sq[row] = s;
}

// ---------------------------------------------------------------------------
// Kernel 1b: init hard-neg accumulators to +inf bits.
// ---------------------------------------------------------------------------
__global__ void init_kernel() {
    int i = blockIdx.x * 256 + threadIdx.x;
    if (i < NPART * MM) g_hn[i] = 0x7f800000u;
}

// ---------------------------------------------------------------------------
// Kernel 2: CTA = (tile pair t -> (a,b) with a<=b, part n). Computes the
// 64x64 gram block via split-bf16 mma.sync (K=256, 8 k-chunks of 32,
// double-buffered cp.async). Epilogue: dist, per-tile sum, row-mins for
// group a, col-mins for group b (transpose), hard-pos on diagonal tiles.
// ---------------------------------------------------------------------------
__global__ void __launch_bounds__(256) gemm_kernel() {
    extern __shared__ char smem[];
    uint32_t sb = smem_u32(smem);
    const int tid  = threadIdx.x;
    const int wid  = tid >> 5;
    const int lane = tid & 31;
    const int wr = wid >> 2;           // 0..1 : 32-row group
    const int wc = wid & 3;            // 0..3 : 16-col group
    const int t = blockIdx.x;
    const int n = blockIdx.y;
    int a, b; tile_pair(t, a, b);
    const bool diag = (a == b);

    const __nv_bfloat16* hi_n = g_hi + (size_t)n * MM * DD;
    const __nv_bfloat16* lo_n = g_lo + (size_t)n * MM * DD;

    // ---- prologue: sq for both groups + k-chunk 0 ----
    if (tid < 32) {
        int grp = (tid < 16) ? a : b;
        int q = tid & 15;
        cp16(sb + SM_SQ + tid * 16, g_sq + n * MM + grp * 64 + q * 4);
    }
#pragma unroll
    for (int c = tid; c < 1024; c += 256) {
        int plane = c >> 8, idx = c & 255;
        int r = idx >> 2, q = idx & 3;
        int grp = (plane < 2) ? a : b;
        const __nv_bfloat16* src =
            ((plane & 1) ? lo_n : hi_n) + (size_t)(grp * 64 + r) * DD + q * 8;
        cp16(sb + plane * PLANE + r * 80 + q * 16, src);
    }
    CP_COMMIT();

    const uint32_t a_off = (uint32_t)(lane & 15) * 80 + (uint32_t)(lane >> 4) * 16;
    const uint32_t b_off = (uint32_t)(wc * 16 + (lane & 7) + ((lane >> 4) & 1) * 8) * 80
                         + (uint32_t)((lane >> 3) & 1) * 16;

    float acc[2][2][4];
#pragma unroll
    for (int mi = 0; mi < 2; mi++)
#pragma unroll
        for (int ni = 0; ni < 2; ni++)
#pragma unroll
            for (int r = 0; r < 4; r++) acc[mi][ni][r] = 0.f;

#pragma unroll 1
    for (int s = 0; s < 8; s++) {
        if (s < 7) {
            const int k0 = (s + 1) * 32;
            const uint32_t bufn = (uint32_t)((s + 1) & 1) * BUFSZ;
#pragma unroll
            for (int c = tid; c < 1024; c += 256) {
                int plane = c >> 8, idx = c & 255;
                int r = idx >> 2, q = idx & 3;
                int grp = (plane < 2) ? a : b;
                const __nv_bfloat16* src =
                    ((plane & 1) ? lo_n : hi_n) + (size_t)(grp * 64 + r) * DD + k0 + q * 8;
                cp16(sb + bufn + plane * PLANE + r * 80 + q * 16, src);
            }
            CP_COMMIT();
            CP_WAIT(1);
        } else {
            CP_WAIT(0);
        }
        __syncthreads();

        const uint32_t bufb = sb + (uint32_t)(s & 1) * BUFSZ;
#pragma unroll
        for (int ks = 0; ks < 2; ks++) {
            uint32_t ahi[2][4], alo[2][4], bhi[4], blo[4];
#pragma unroll
            for (int mi = 0; mi < 2; mi++) {
                uint32_t ra = bufb + (uint32_t)(wr * 32 + mi * 16) * 80 + a_off + ks * 32;
                ldm_x4(ahi[mi], ra);
                ldm_x4(alo[mi], ra + PLANE);
            }
            {
                uint32_t rb = bufb + 2 * PLANE + b_off + ks * 32;
                ldm_x4(bhi, rb);
                ldm_x4(blo, rb + PLANE);
            }
#pragma unroll
            for (int mi = 0; mi < 2; mi++)
#pragma unroll
                for (int ni = 0; ni < 2; ni++) {
                    const int o = ni * 2;
                    mma16816(acc[mi][ni], ahi[mi], &bhi[o]);
                    mma16816(acc[mi][ni], ahi[mi], &blo[o]);
                    mma16816(acc[mi][ni], alo[mi], &bhi[o]);
                }
        }
        __syncthreads();
    }

    // ---- epilogue ----
    const float* sq_s = (const float*)(smem + SM_SQ);
    float rmin[4], rmax[4], cmin[4];
#pragma unroll
    for (int i = 0; i < 4; i++) { rmin[i] = FLT_MAX; rmax[i] = -FLT_MAX; cmin[i] = FLT_MAX; }
    float dsum = 0.f;

#pragma unroll
    for (int mi = 0; mi < 2; mi++)
#pragma unroll
        for (int ni = 0; ni < 2; ni++)
#pragma unroll
            for (int r = 0; r < 4; r++) {
                const int rowl = wr * 32 + mi * 16 + (r >> 1) * 8 + (lane >> 2);
                const int col  = wc * 16 + ni * 8 + (lane & 3) * 2 + (r & 1);
                float d2 = sq_s[rowl] + sq_s[64 + col] - 2.f * acc[mi][ni][r];
                float dist = sqrtf(fmaxf(d2, 0.f));
                dsum += dist;
                const int rs = mi * 2 + (r >> 1);
                const int cs = ni * 2 + (r & 1);
                if (diag) {
                    if ((rowl >> 3) == (col >> 3)) rmax[rs] = fmaxf(rmax[rs], dist);
                    else                           rmin[rs] = fminf(rmin[rs], dist);
                } else {
                    rmin[rs] = fminf(rmin[rs], dist);
                    cmin[cs] = fminf(cmin[cs], dist);
                }
            }

    float* rowmin = (float*)(smem + SM_ROWMIN);
    float* rowmax = (float*)(smem + SM_ROWMAX);
    float* colmin = (float*)(smem + SM_COLMIN);
    float* rsum   = (float*)(smem + SM_RSUM);

#pragma unroll
    for (int s2 = 0; s2 < 4; s2++) {
        float rm = rmin[s2], rx = rmax[s2];
        rm = fminf(rm, __shfl_xor_sync(0xFFFFFFFFu, rm, 1));
        rm = fminf(rm, __shfl_xor_sync(0xFFFFFFFFu, rm, 2));
        rx = fmaxf(rx, __shfl_xor_sync(0xFFFFFFFFu, rx, 1));
        rx = fmaxf(rx, __shfl_xor_sync(0xFFFFFFFFu, rx, 2));
        if ((lane & 3) == 0) {
            const int row = wr * 32 + (s2 >> 1) * 16 + (s2 & 1) * 8 + (lane >> 2);
            rowmin[row * 4 + wc] = rm;
            rowmax[row * 4 + wc] = rx;
        }
        float cm = cmin[s2];
        cm = fminf(cm, __shfl_xor_sync(0xFFFFFFFFu, cm, 4));
        cm = fminf(cm, __shfl_xor_sync(0xFFFFFFFFu, cm, 8));
        cm = fminf(cm, __shfl_xor_sync(0xFFFFFFFFu, cm, 16));
        if (lane < 4) {
            const int col = wc * 16 + (s2 >> 1) * 8 + (lane & 3) * 2 + (s2 & 1);
            colmin[col * 2 + wr] = cm;
        }
    }
    rsum[tid] = dsum;
    __syncthreads();

    if (tid < 64) {
        float rn = FLT_MAX, rp = -FLT_MAX;
#pragma unroll
        for (int c = 0; c < 4; c++) {
            rn = fminf(rn, rowmin[tid * 4 + c]);
            rp = fmaxf(rp, rowmax[tid * 4 + c]);
        }
        const int gidx = n * MM + a * 64 + tid;
        atomicMin(&g_hn[gidx], __float_as_uint(rn));
        if (diag) g_hp[gidx] = rp;
    } else if (tid < 128 && !diag) {
        const int j = tid - 64;
        float cm = fminf(colmin[j * 2], colmin[j * 2 + 1]);
        atomicMin(&g_hn[n * MM + b * 64 + j], __float_as_uint(cm));
    }
    __syncthreads();
    for (int s = 128; s > 0; s >>= 1) {
        if (tid < s) rsum[tid] += rsum[tid + s];
        __syncthreads();
    }
    if (tid == 0) g_dsum[n * NTILE + t] = rsum[0];
}

// ---------------------------------------------------------------------------
// Kernel 3: per part: loss mean from hp/hn, dist mean from tile sums
// (off-diagonal tiles count twice). Fixed-order sums -> deterministic.
// ---------------------------------------------------------------------------
__global__ void finish_kernel(float* __restrict__ out) {
    __shared__ float ls[256];
    __shared__ float ds[64];
    const int n = blockIdx.x;
    const int tid = threadIdx.x;
    float l = 0.f;
#pragma unroll
    for (int h = 0; h < 2; h++) {
        int i = n * MM + tid + h * 256;
        float hn = __uint_as_float(g_hn[i]);
        l += fmaxf(MARGIN + g_hp[i] - hn, 0.f);
    }
    ls[tid] = l;
    if (tid < 64) {
        float d = 0.f;
        if (tid < NTILE) {
            int aa, bb; tile_pair(tid, aa, bb);
            d = g_dsum[n * NTILE + tid] * ((aa == bb) ? 1.f : 2.f);
        }
        ds[tid] = d;
    }
    __syncthreads();
    for (int s = 128; s > 0; s >>= 1) {
        if (tid < s) ls[tid] += ls[tid + s];
        __syncthreads();
    }
    for (int s = 32; s > 0; s >>= 1) {
        if (tid < s) ds[tid] += ds[tid + s];
        __syncthreads();
    }
    if (tid == 0) {
        out[n]         = ls[0] / (float)MM;
        out[NPART + n] = ds[0] / ((float)MM * (float)MM);
    }
}

extern "C" void kernel_launch(void* const* d_in, const int* in_sizes, int n_in,
                              void* d_out, int out_size) {
    const float* feature = (const float*)d_in[0];
    float* out = (float*)d_out;

    cudaFuncSetAttribute(gemm_kernel, cudaFuncAttributeMaxDynamicSharedMemorySize, SM_TOTAL);

    dim3 b1(32, 8);
    prep_kernel<<<(NPART * MM + 7) / 8, b1>>>(feature);
    init_kernel<<<(NPART * MM + 255) / 256, 256>>>();

    dim3 grid(NTILE, NPART);
    gemm_kernel<<<grid, 256, SM_TOTAL>>>();

    finish_kernel<<<NPART, 256>>>(out);
}